// round 15
// baseline (speedup 1.0000x reference)
#include <cuda_runtime.h>
#include <cuda_bf16.h>
#include <math.h>

#define N_NODES 8192
#define IN_DIM  512
#define H_DIM   128
#define MASK_WPR (N_NODES / 32)   // 256 mask words per row

// MMA tile constants
#define RT 64
#define CT 128
#define NTH 256
#define APAD 136
#define ROWB (APAD * 2)
#define AS_BYTES (RT * APAD * 2)           // 17408
#define BS_BYTES (CT * APAD * 2)           // 34816

#define JSPLIT 4
#define CHUNKS (N_NODES / CT / JSPLIT)     // 16 chunks per fused CTA

// fused smem: As double + Bs single + tables -> 3 CTAs/SM
#define F_BS_OFF (2 * AS_BYTES)            // 34816
#define F_SL_OFF (F_BS_OFF + BS_BYTES)     // 69632
#define F_SMEM   (F_SL_OFF + 2 * RT * 4)   // 70144

// Scratch (allocation-free: __device__ globals)
__device__ __nv_bfloat16 g_Whb [(size_t)N_NODES * H_DIM];    // 2 MB bf16, row-major
__device__ __nv_bfloat16 g_WbT [(size_t)IN_DIM * H_DIM];     // 128 KB bf16 (W^T, k-major)
__device__ float         g_E   [N_NODES];
__device__ float         g_E2  [N_NODES];
__device__ float         g_inv [N_NODES];
__device__ float         g_wa  [IN_DIM];
__device__ unsigned      g_mask[(size_t)N_NODES * MASK_WPR];        // 8 MB
__device__ float         g_part[(size_t)JSPLIT * N_NODES * H_DIM];  // 16 MB

// ---------------------------------------------------------------------------
// helpers
// ---------------------------------------------------------------------------
__device__ __forceinline__ void mma16816(float* c, const unsigned* a,
                                         unsigned b0, unsigned b1) {
    asm volatile(
        "mma.sync.aligned.m16n8k16.row.col.f32.bf16.bf16.f32 "
        "{%0,%1,%2,%3}, {%4,%5,%6,%7}, {%8,%9}, {%0,%1,%2,%3};"
        : "+f"(c[0]), "+f"(c[1]), "+f"(c[2]), "+f"(c[3])
        : "r"(a[0]), "r"(a[1]), "r"(a[2]), "r"(a[3]), "r"(b0), "r"(b1));
}

__device__ __forceinline__ void cp16(unsigned dst, const void* src) {
    asm volatile("cp.async.cg.shared.global [%0], [%1], 16;\n"
                 :: "r"(dst), "l"(src));
}

// ---------------------------------------------------------------------------
// Kernel 0 (merged): blocks 0..255 -> WbT[k][n] = bf16(W[n][k]);
//                    block 256     -> wa = W^T @ a
// ---------------------------------------------------------------------------
__global__ __launch_bounds__(256) void k_prep(const float* __restrict__ W,
                                              const float* __restrict__ a) {
    if (blockIdx.x < 256) {
        int idx = blockIdx.x * 256 + threadIdx.x;
        int k = idx >> 7, n = idx & 127;
        g_WbT[idx] = __float2bfloat16(W[(size_t)n * IN_DIM + k]);
    } else {
#pragma unroll
        for (int half = 0; half < 2; half++) {
            int k = threadIdx.x + half * 256;
            float sum = 0.f;
#pragma unroll 4
            for (int hd = 0; hd < H_DIM; hd++)
                sum += a[hd] * W[(size_t)hd * IN_DIM + k];
            g_wa[k] = sum;
        }
    }
}

// ---------------------------------------------------------------------------
// Kernel 1: s = h.wa ; E = exp(s), E2 = exp(0.2 s)
// ---------------------------------------------------------------------------
__global__ __launch_bounds__(256) void k_s(const float* __restrict__ h) {
    int row  = (blockIdx.x * blockDim.x + threadIdx.x) >> 5;
    int lane = threadIdx.x & 31;
    const float4* h4  = (const float4*)(h + (size_t)row * IN_DIM);
    const float4* wa4 = (const float4*)g_wa;
    float d = 0.f;
#pragma unroll
    for (int u = 0; u < 4; u++) {
        float4 x = h4[lane + 32 * u];
        float4 y = __ldg(&wa4[lane + 32 * u]);
        d += x.x * y.x + x.y * y.y + x.z * y.z + x.w * y.w;
    }
#pragma unroll
    for (int o = 16; o; o >>= 1) d += __shfl_xor_sync(0xffffffffu, d, o);
    if (lane == 0) {
        g_E [row] = __expf(d);
        g_E2[row] = __expf(0.2f * d);
    }
}

// ---------------------------------------------------------------------------
// Kernel 2: Whb = bf16(h @ W^T + b) via mma.sync (proven R9 version, 17us)
// ---------------------------------------------------------------------------
#define GT_SMEM (2 * AS_BYTES + 2 * BS_BYTES + H_DIM * 4)

__global__ __launch_bounds__(NTH, 2) void k_gemm_tc(const float* __restrict__ h,
                                                    const float* __restrict__ b) {
    extern __shared__ char smem[];
    __nv_bfloat16* As = (__nv_bfloat16*)smem;
    float* sbias = (float*)(smem + 2 * AS_BYTES + 2 * BS_BYTES);

    const int t    = threadIdx.x;
    const int lane = t & 31;
    const int wid  = t >> 5;
    const int m0   = blockIdx.x * RT;

    const unsigned as_base = (unsigned)__cvta_generic_to_shared(As);
    const unsigned bs_base = (unsigned)__cvta_generic_to_shared(smem + 2 * AS_BYTES);

    if (t < H_DIM) sbias[t] = b[t];

    float4 av[8];
#pragma unroll
    for (int p = 0; p < 8; p++) {
        int idx = t + p * NTH;
        int r = idx >> 5, c4 = idx & 31;
        av[p] = __ldg((const float4*)(h + (size_t)(m0 + r) * IN_DIM) + c4);
    }
#pragma unroll
    for (int p = 0; p < 8; p++) {
        int idx = t + p * NTH;
        int jr = idx >> 4, u = idx & 15;
        cp16(bs_base + jr * ROWB + u * 16, (const char*)g_WbT + idx * 16);
    }
    asm volatile("cp.async.commit_group;");
#pragma unroll
    for (int p = 0; p < 8; p++) {
        int idx = t + p * NTH;
        int r = idx >> 5, c4 = idx & 31;
        __nv_bfloat162* dst = (__nv_bfloat162*)&As[r * APAD + c4 * 4];
        dst[0] = __float22bfloat162_rn(make_float2(av[p].x, av[p].y));
        dst[1] = __float22bfloat162_rn(make_float2(av[p].z, av[p].w));
    }
    asm volatile("cp.async.wait_group 0;");
    __syncthreads();

    const int wm = wid >> 1;
    const int wn = wid & 1;
    float acc[8][4];
#pragma unroll
    for (int n = 0; n < 8; n++)
#pragma unroll
        for (int c = 0; c < 4; c++) acc[n][c] = 0.f;

    const unsigned a_off0 = (wm * 16 + (lane & 15)) * ROWB + ((lane >> 4) * 8) * 2;
    const unsigned b_rowsel = (lane & 15);
    const unsigned b_colsel = (lane >> 4) * 8;

#pragma unroll
    for (int c = 0; c < IN_DIM / CT; c++) {
        const int buf = c & 1;
        if (c + 1 < IN_DIM / CT) {
#pragma unroll
            for (int p = 0; p < 8; p++) {
                int idx = t + p * NTH;
                int r = idx >> 5, c4 = idx & 31;
                av[p] = __ldg((const float4*)(h + (size_t)(m0 + r) * IN_DIM
                                              + (c + 1) * CT) + c4);
            }
            const char* src = (const char*)(g_WbT + (size_t)(c + 1) * CT * H_DIM);
            const unsigned bdst = bs_base + (buf ^ 1) * BS_BYTES;
#pragma unroll
            for (int p = 0; p < 8; p++) {
                int idx = t + p * NTH;
                int jr = idx >> 4, u = idx & 15;
                cp16(bdst + jr * ROWB + u * 16, src + idx * 16);
            }
            asm volatile("cp.async.commit_group;");
        }

        const unsigned abuf = as_base + buf * AS_BYTES + a_off0;
        const unsigned bbuf = bs_base + buf * BS_BYTES;
#pragma unroll
        for (int kk = 0; kk < CT; kk += 16) {
            unsigned a[4];
            asm volatile(
                "ldmatrix.sync.aligned.m8n8.x4.shared.b16 {%0,%1,%2,%3}, [%4];"
                : "=r"(a[0]), "=r"(a[1]), "=r"(a[2]), "=r"(a[3])
                : "r"(abuf + kk * 2));
#pragma unroll
            for (int nt = 0; nt < 4; nt++) {
                int n0 = wn * 64 + nt * 16;
                unsigned baddr = bbuf + (kk + b_rowsel) * ROWB
                                      + (n0 + b_colsel) * 2;
                unsigned bb[4];
                asm volatile(
                    "ldmatrix.sync.aligned.m8n8.x4.trans.shared.b16 "
                    "{%0,%1,%2,%3}, [%4];"
                    : "=r"(bb[0]), "=r"(bb[1]), "=r"(bb[2]), "=r"(bb[3])
                    : "r"(baddr));
                mma16816(acc[nt * 2 + 0], a, bb[0], bb[1]);
                mma16816(acc[nt * 2 + 1], a, bb[2], bb[3]);
            }
        }

        if (c + 1 < IN_DIM / CT) {
            __nv_bfloat16* Ad = As + (buf ^ 1) * (RT * APAD);
#pragma unroll
            for (int p = 0; p < 8; p++) {
                int idx = t + p * NTH;
                int r = idx >> 5, c4 = idx & 31;
                __nv_bfloat162* dst = (__nv_bfloat162*)&Ad[r * APAD + c4 * 4];
                dst[0] = __float22bfloat162_rn(make_float2(av[p].x, av[p].y));
                dst[1] = __float22bfloat162_rn(make_float2(av[p].z, av[p].w));
            }
            asm volatile("cp.async.wait_group 0;");
        }
        __syncthreads();
    }

    const int g = lane >> 2, q = lane & 3;
    const int r0 = m0 + wm * 16 + g;
    const int r1 = r0 + 8;
#pragma unroll
    for (int m = 0; m < 8; m++) {
        int col = wn * 64 + m * 8 + 2 * q;
        g_Whb[(size_t)r0 * H_DIM + col]     = __float2bfloat16(acc[m][0] + sbias[col]);
        g_Whb[(size_t)r0 * H_DIM + col + 1] = __float2bfloat16(acc[m][1] + sbias[col + 1]);
        g_Whb[(size_t)r1 * H_DIM + col]     = __float2bfloat16(acc[m][2] + sbias[col]);
        g_Whb[(size_t)r1 * H_DIM + col + 1] = __float2bfloat16(acc[m][3] + sbias[col + 1]);
    }
}

// ---------------------------------------------------------------------------
// Kernel 3: per-row denom + bitmask (max-trick, branch-free, dual accumulators)
// ---------------------------------------------------------------------------
__global__ __launch_bounds__(256) void k_denom(const float* __restrict__ adj) {
    const int i    = blockIdx.x;
    const int t    = threadIdx.x;
    const int lane = t & 31;
    const int wid  = t >> 5;

    const float Ei  = __ldg(&g_E[i]);
    const float E2i = __ldg(&g_E2[i]);
    const float4* __restrict__ row4 = (const float4*)(adj + (size_t)i * N_NODES);
    const float4* __restrict__ E4   = (const float4*)g_E;
    const float4* __restrict__ E24  = (const float4*)g_E2;
    uint4* __restrict__ mrow = (uint4*)(g_mask + (size_t)i * MASK_WPR);

    float dsum0 = 0.f, dsum1 = 0.f;
#pragma unroll
    for (int step = 0; step < 8; step++) {
        int grp = wid * 8 + step;
        int c4  = grp * 32 + lane;
        float4 a4  = __ldcs(&row4[c4]);
        float4 Ej  = __ldg(&E4[c4]);
        float4 E2j = __ldg(&E24[c4]);
        unsigned nib = (a4.x != 0.f) | ((a4.y != 0.f) << 1)
                     | ((a4.z != 0.f) << 2) | ((a4.w != 0.f) << 3);
        unsigned b0 = __ballot_sync(0xffffffffu, nib & 1u);
        unsigned b1 = __ballot_sync(0xffffffffu, nib & 2u);
        unsigned b2 = __ballot_sync(0xffffffffu, nib & 4u);
        unsigned b3 = __ballot_sync(0xffffffffu, nib & 8u);
        if (lane == 0) mrow[grp] = make_uint4(b0, b1, b2, b3);

        dsum0 = fmaf(a4.x, fmaxf(Ei * Ej.x, E2i * E2j.x), dsum0);
        dsum1 = fmaf(a4.y, fmaxf(Ei * Ej.y, E2i * E2j.y), dsum1);
        dsum0 = fmaf(a4.z, fmaxf(Ei * Ej.z, E2i * E2j.z), dsum0);
        dsum1 = fmaf(a4.w, fmaxf(Ei * Ej.w, E2i * E2j.w), dsum1);
    }
    float dsum = dsum0 + dsum1;
#pragma unroll
    for (int o = 16; o; o >>= 1) dsum += __shfl_xor_sync(0xffffffffu, dsum, o);
    __shared__ float red[8];
    if (lane == 0) red[wid] = dsum;
    __syncthreads();
    if (t == 0) {
        float tot = 0.f;
#pragma unroll
        for (int w = 0; w < 8; w++) tot += red[w];
        g_inv[i] = (tot > 0.f) ? 1.f / tot : 0.f;
    }
}

// ---------------------------------------------------------------------------
// Kernel 4 (fused): RT=64, CT=128, 256 thr, JSPLIT=4 (grid 512), 3 CTAs/SM.
// As double-buffered, Bs single-buffered; Bs reload latency covered by
// alpha compute; extra stalls covered by 3rd co-resident CTA.
// ---------------------------------------------------------------------------
__device__ __forceinline__ void alpha_tile(
    __nv_bfloat16* Ad, float* __restrict__ alpha_out,
    const uint4* m4g, const float4* E4g, const float4* E24g,
    const float* sEA, const float* sEB,
    int i0, int jc, int wid, int lane)
{
    float4 Ej  = __ldg(&E4g [jc * 32 + lane]);
    float4 E2j = __ldg(&E24g[jc * 32 + lane]);
#pragma unroll
    for (int p = 0; p < 8; p++) {
        int r = wid * 8 + p;
        uint4 mw = __ldg(&m4g[(size_t)(i0 + r) * (MASK_WPR / 4) + jc]);
        float eA = sEA[r], eB = sEB[r];
        float4 ex;
        ex.x = ((mw.x >> lane) & 1u) ? fmaxf(eA * Ej.x, eB * E2j.x) : 0.f;
        ex.y = ((mw.y >> lane) & 1u) ? fmaxf(eA * Ej.y, eB * E2j.y) : 0.f;
        ex.z = ((mw.z >> lane) & 1u) ? fmaxf(eA * Ej.z, eB * E2j.z) : 0.f;
        ex.w = ((mw.w >> lane) & 1u) ? fmaxf(eA * Ej.w, eB * E2j.w) : 0.f;
        __stcs((float4*)(alpha_out + (size_t)(i0 + r) * N_NODES
                         + (size_t)jc * CT) + lane, ex);
        __nv_bfloat162* dst = (__nv_bfloat162*)&Ad[r * APAD + lane * 4];
        dst[0] = __float22bfloat162_rn(make_float2(ex.x, ex.y));
        dst[1] = __float22bfloat162_rn(make_float2(ex.z, ex.w));
    }
}

__global__ __launch_bounds__(NTH, 3) void k_fused(float* __restrict__ alpha_out) {
    extern __shared__ char smem[];
    __nv_bfloat16* As  = (__nv_bfloat16*)smem;            // 2 buffers
    float*         sEA = (float*)(smem + F_SL_OFF);       // E[i]*inv
    float*         sEB = sEA + RT;                        // E2[i]*inv

    const int t    = threadIdx.x;
    const int lane = t & 31;
    const int wid  = t >> 5;                 // 0..7
    const int ib   = blockIdx.x & 127;
    const int js   = blockIdx.x >> 7;        // 0..3
    const int i0   = ib * RT;
    const int c0   = js * CHUNKS;

    const unsigned as_base = (unsigned)__cvta_generic_to_shared(As);
    const unsigned bs_base = (unsigned)__cvta_generic_to_shared(smem + F_BS_OFF);

    if (t < RT) {
        float inv = g_inv[i0 + t];
        sEA[t] = g_E [i0 + t] * inv;
        sEB[t] = g_E2[i0 + t] * inv;
    }

    // prologue: Bs chunk c0 (single buffer)
    {
        const char* src = (const char*)(g_Whb + (size_t)c0 * CT * H_DIM);
#pragma unroll
        for (int p = 0; p < 8; p++) {
            int idx = t + p * NTH;
            int jr = idx >> 4, u = idx & 15;
            cp16(bs_base + jr * ROWB + u * 16, src + idx * 16);
        }
        asm volatile("cp.async.commit_group;");
    }
    __syncthreads();   // tables ready

    const float4* E4g  = (const float4*)g_E;
    const float4* E24g = (const float4*)g_E2;
    const uint4*  m4g  = (const uint4*)g_mask;

    // alpha chunk c0 -> As[0]
    alpha_tile(As, alpha_out, m4g, E4g, E24g, sEA, sEB, i0, c0, wid, lane);
    asm volatile("cp.async.wait_group 0;");
    __syncthreads();

    const int wm = wid >> 1;     // 0..3 -> rows wm*16
    const int wn = wid & 1;      // 0..1 -> cols wn*64
    float acc[8][4];
#pragma unroll
    for (int n = 0; n < 8; n++)
#pragma unroll
        for (int c = 0; c < 4; c++) acc[n][c] = 0.f;

    const unsigned a_off0 = (wm * 16 + (lane & 15)) * ROWB + ((lane >> 4) * 8) * 2;
    const unsigned b_rowsel = (lane & 15);
    const unsigned b_colsel = (lane >> 4) * 8;

    for (int cc = 0; cc < CHUNKS; cc++) {
        const int buf = cc & 1;
        const int jc  = c0 + cc;

        // MMA on As[buf] x Bs (chunk cc)
        const unsigned abuf = as_base + buf * AS_BYTES + a_off0;
#pragma unroll
        for (int kk = 0; kk < CT; kk += 16) {
            unsigned a[4];
            asm volatile(
                "ldmatrix.sync.aligned.m8n8.x4.shared.b16 {%0,%1,%2,%3}, [%4];"
                : "=r"(a[0]), "=r"(a[1]), "=r"(a[2]), "=r"(a[3])
                : "r"(abuf + kk * 2));
#pragma unroll
            for (int nt = 0; nt < 4; nt++) {
                int n0 = wn * 64 + nt * 16;
                unsigned baddr = bs_base + (kk + b_rowsel) * ROWB
                                         + (n0 + b_colsel) * 2;
                unsigned bb[4];
                asm volatile(
                    "ldmatrix.sync.aligned.m8n8.x4.trans.shared.b16 "
                    "{%0,%1,%2,%3}, [%4];"
                    : "=r"(bb[0]), "=r"(bb[1]), "=r"(bb[2]), "=r"(bb[3])
                    : "r"(baddr));
                mma16816(acc[nt * 2 + 0], a, bb[0], bb[1]);
                mma16816(acc[nt * 2 + 1], a, bb[2], bb[3]);
            }
        }

        if (cc + 1 < CHUNKS) {
            __syncthreads();   // all warps done with Bs(cc) and As writes safe

            // issue Bs(cc+1) reload, then cover its latency with alpha compute
            const char* src = (const char*)(g_Whb + (size_t)(jc + 1) * CT * H_DIM);
#pragma unroll
            for (int p = 0; p < 8; p++) {
                int idx = t + p * NTH;
                int jr = idx >> 4, u = idx & 15;
                cp16(bs_base + jr * ROWB + u * 16, src + idx * 16);
            }
            asm volatile("cp.async.commit_group;");

            alpha_tile(As + (buf ^ 1) * (RT * APAD), alpha_out,
                       m4g, E4g, E24g, sEA, sEB, i0, jc + 1, wid, lane);

            asm volatile("cp.async.wait_group 0;");
            __syncthreads();
        }
    }

    // epilogue: write fp32 partials
    float* part = g_part + (size_t)js * N_NODES * H_DIM;
    const int g = lane >> 2, q = lane & 3;
    const size_t r0 = (size_t)(i0 + wm * 16 + g) * H_DIM;
    const size_t r1 = r0 + 8 * H_DIM;
#pragma unroll
    for (int m = 0; m < 8; m++) {
        int col = wn * 64 + m * 8 + 2 * q;
        part[r0 + col]     = acc[m][0];
        part[r0 + col + 1] = acc[m][1];
        part[r1 + col]     = acc[m][2];
        part[r1 + col + 1] = acc[m][3];
    }
}

// ---------------------------------------------------------------------------
// Kernel 5: z = sigmoid(sum of JSPLIT partials)
// ---------------------------------------------------------------------------
__global__ __launch_bounds__(256) void k_z(float* __restrict__ z_out) {
    int idx = blockIdx.x * 256 + threadIdx.x;
    float4 acc = ((const float4*)g_part)[idx];
#pragma unroll
    for (int js = 1; js < JSPLIT; js++) {
        float4 v = ((const float4*)(g_part + (size_t)js * N_NODES * H_DIM))[idx];
        acc.x += v.x; acc.y += v.y; acc.z += v.z; acc.w += v.w;
    }
    float4 z;
    z.x = 1.f / (1.f + __expf(-acc.x));
    z.y = 1.f / (1.f + __expf(-acc.y));
    z.z = 1.f / (1.f + __expf(-acc.z));
    z.w = 1.f / (1.f + __expf(-acc.w));
    ((float4*)z_out)[idx] = z;
}

// ---------------------------------------------------------------------------
extern "C" void kernel_launch(void* const* d_in, const int* in_sizes, int n_in,
                              void* d_out, int out_size) {
    const float* h   = (const float*)d_in[0];  // (8192, 512)
    const float* adj = (const float*)d_in[1];  // (8192, 8192)
    const float* W   = (const float*)d_in[2];  // (128, 512)
    const float* b   = (const float*)d_in[3];  // (128,)
    const float* a   = (const float*)d_in[4];  // (1, 128)

    float* z_out     = (float*)d_out;
    float* alpha_out = z_out + (size_t)N_NODES * H_DIM;

    k_prep<<<257, 256>>>(W, a);
    k_s<<<N_NODES / 8, 256>>>(h);

    cudaFuncSetAttribute(k_gemm_tc, cudaFuncAttributeMaxDynamicSharedMemorySize,
                         GT_SMEM);
    k_gemm_tc<<<N_NODES / RT, NTH, GT_SMEM>>>(h, b);

    k_denom<<<N_NODES, 256>>>(adj);

    cudaFuncSetAttribute(k_fused, cudaFuncAttributeMaxDynamicSharedMemorySize,
                         F_SMEM);
    k_fused<<<(N_NODES / RT) * JSPLIT, NTH, F_SMEM>>>(alpha_out);

    k_z<<<(N_NODES * H_DIM / 4) / 256, 256>>>(z_out);
}

// round 16
// speedup vs baseline: 1.0796x; 1.0796x over previous
#include <cuda_runtime.h>
#include <cuda_bf16.h>
#include <math.h>

#define N_NODES 8192
#define IN_DIM  512
#define H_DIM   128
#define MASK_WPR (N_NODES / 32)   // 256 mask words per row

// MMA tile constants
#define RT 64
#define CT 128
#define NTH 256
#define APAD 136
#define ROWB (APAD * 2)
#define AS_BYTES (RT * APAD * 2)           // 17408
#define BS_BYTES (CT * APAD * 2)           // 34816

#define JSPLIT 8
#define CHUNKS (N_NODES / CT / JSPLIT)     // 8 chunks per unit
#define NUNITS (128 * JSPLIT)              // 1024 work units
#define PGRID  304                         // persistent CTAs (2 x 152 SMs)

// fused smem: As double + Bs double + tables + unit slot (R9 layout)
#define OFF_BS   (2 * AS_BYTES)
#define OFF_SL   (OFF_BS + 2 * BS_BYTES)
#define SMEM_TOTAL (OFF_SL + 2 * RT * 4 + 16)

// Scratch (allocation-free: __device__ globals)
__device__ __nv_bfloat16 g_Whb [(size_t)N_NODES * H_DIM];    // 2 MB bf16, row-major
__device__ __nv_bfloat16 g_WbT [(size_t)IN_DIM * H_DIM];     // 128 KB bf16 (W^T, k-major)
__device__ float         g_E   [N_NODES];
__device__ float         g_E2  [N_NODES];
__device__ float         g_inv [N_NODES];
__device__ float         g_wa  [IN_DIM];
__device__ unsigned      g_mask[(size_t)N_NODES * MASK_WPR];        // 8 MB
__device__ float         g_part[(size_t)JSPLIT * N_NODES * H_DIM];  // 32 MB
__device__ unsigned      g_ctr;                                      // work queue

// ---------------------------------------------------------------------------
// helpers
// ---------------------------------------------------------------------------
__device__ __forceinline__ void mma16816(float* c, const unsigned* a,
                                         unsigned b0, unsigned b1) {
    asm volatile(
        "mma.sync.aligned.m16n8k16.row.col.f32.bf16.bf16.f32 "
        "{%0,%1,%2,%3}, {%4,%5,%6,%7}, {%8,%9}, {%0,%1,%2,%3};"
        : "+f"(c[0]), "+f"(c[1]), "+f"(c[2]), "+f"(c[3])
        : "r"(a[0]), "r"(a[1]), "r"(a[2]), "r"(a[3]), "r"(b0), "r"(b1));
}

__device__ __forceinline__ void cp16(unsigned dst, const void* src) {
    asm volatile("cp.async.cg.shared.global [%0], [%1], 16;\n"
                 :: "r"(dst), "l"(src));
}

// ---------------------------------------------------------------------------
// Kernel 0 (merged): blocks 0..255 -> WbT transpose; block 256 -> wa + ctr reset
// ---------------------------------------------------------------------------
__global__ __launch_bounds__(256) void k_prep(const float* __restrict__ W,
                                              const float* __restrict__ a) {
    if (blockIdx.x < 256) {
        int idx = blockIdx.x * 256 + threadIdx.x;
        int k = idx >> 7, n = idx & 127;
        g_WbT[idx] = __float2bfloat16(W[(size_t)n * IN_DIM + k]);
    } else {
        if (threadIdx.x == 0) g_ctr = 0;   // reset fused work queue each launch
#pragma unroll
        for (int half = 0; half < 2; half++) {
            int k = threadIdx.x + half * 256;
            float sum = 0.f;
#pragma unroll 4
            for (int hd = 0; hd < H_DIM; hd++)
                sum += a[hd] * W[(size_t)hd * IN_DIM + k];
            g_wa[k] = sum;
        }
    }
}

// ---------------------------------------------------------------------------
// Kernel 1: s = h.wa ; E = exp(s), E2 = exp(0.2 s)
// ---------------------------------------------------------------------------
__global__ __launch_bounds__(256) void k_s(const float* __restrict__ h) {
    int row  = (blockIdx.x * blockDim.x + threadIdx.x) >> 5;
    int lane = threadIdx.x & 31;
    const float4* h4  = (const float4*)(h + (size_t)row * IN_DIM);
    const float4* wa4 = (const float4*)g_wa;
    float d = 0.f;
#pragma unroll
    for (int u = 0; u < 4; u++) {
        float4 x = h4[lane + 32 * u];
        float4 y = __ldg(&wa4[lane + 32 * u]);
        d += x.x * y.x + x.y * y.y + x.z * y.z + x.w * y.w;
    }
#pragma unroll
    for (int o = 16; o; o >>= 1) d += __shfl_xor_sync(0xffffffffu, d, o);
    if (lane == 0) {
        g_E [row] = __expf(d);
        g_E2[row] = __expf(0.2f * d);
    }
}

// ---------------------------------------------------------------------------
// Kernel 2: Whb = bf16(h @ W^T + b) via mma.sync (proven R9 version, 17us)
// ---------------------------------------------------------------------------
#define GT_SMEM (2 * AS_BYTES + 2 * BS_BYTES + H_DIM * 4)

__global__ __launch_bounds__(NTH, 2) void k_gemm_tc(const float* __restrict__ h,
                                                    const float* __restrict__ b) {
    extern __shared__ char smem[];
    __nv_bfloat16* As = (__nv_bfloat16*)smem;
    float* sbias = (float*)(smem + 2 * AS_BYTES + 2 * BS_BYTES);

    const int t    = threadIdx.x;
    const int lane = t & 31;
    const int wid  = t >> 5;
    const int m0   = blockIdx.x * RT;

    const unsigned as_base = (unsigned)__cvta_generic_to_shared(As);
    const unsigned bs_base = (unsigned)__cvta_generic_to_shared(smem + 2 * AS_BYTES);

    if (t < H_DIM) sbias[t] = b[t];

    float4 av[8];
#pragma unroll
    for (int p = 0; p < 8; p++) {
        int idx = t + p * NTH;
        int r = idx >> 5, c4 = idx & 31;
        av[p] = __ldg((const float4*)(h + (size_t)(m0 + r) * IN_DIM) + c4);
    }
#pragma unroll
    for (int p = 0; p < 8; p++) {
        int idx = t + p * NTH;
        int jr = idx >> 4, u = idx & 15;
        cp16(bs_base + jr * ROWB + u * 16, (const char*)g_WbT + idx * 16);
    }
    asm volatile("cp.async.commit_group;");
#pragma unroll
    for (int p = 0; p < 8; p++) {
        int idx = t + p * NTH;
        int r = idx >> 5, c4 = idx & 31;
        __nv_bfloat162* dst = (__nv_bfloat162*)&As[r * APAD + c4 * 4];
        dst[0] = __float22bfloat162_rn(make_float2(av[p].x, av[p].y));
        dst[1] = __float22bfloat162_rn(make_float2(av[p].z, av[p].w));
    }
    asm volatile("cp.async.wait_group 0;");
    __syncthreads();

    const int wm = wid >> 1;
    const int wn = wid & 1;
    float acc[8][4];
#pragma unroll
    for (int n = 0; n < 8; n++)
#pragma unroll
        for (int c = 0; c < 4; c++) acc[n][c] = 0.f;

    const unsigned a_off0 = (wm * 16 + (lane & 15)) * ROWB + ((lane >> 4) * 8) * 2;
    const unsigned b_rowsel = (lane & 15);
    const unsigned b_colsel = (lane >> 4) * 8;

#pragma unroll
    for (int c = 0; c < IN_DIM / CT; c++) {
        const int buf = c & 1;
        if (c + 1 < IN_DIM / CT) {
#pragma unroll
            for (int p = 0; p < 8; p++) {
                int idx = t + p * NTH;
                int r = idx >> 5, c4 = idx & 31;
                av[p] = __ldg((const float4*)(h + (size_t)(m0 + r) * IN_DIM
                                              + (c + 1) * CT) + c4);
            }
            const char* src = (const char*)(g_WbT + (size_t)(c + 1) * CT * H_DIM);
            const unsigned bdst = bs_base + (buf ^ 1) * BS_BYTES;
#pragma unroll
            for (int p = 0; p < 8; p++) {
                int idx = t + p * NTH;
                int jr = idx >> 4, u = idx & 15;
                cp16(bdst + jr * ROWB + u * 16, src + idx * 16);
            }
            asm volatile("cp.async.commit_group;");
        }

        const unsigned abuf = as_base + buf * AS_BYTES + a_off0;
        const unsigned bbuf = bs_base + buf * BS_BYTES;
#pragma unroll
        for (int kk = 0; kk < CT; kk += 16) {
            unsigned a[4];
            asm volatile(
                "ldmatrix.sync.aligned.m8n8.x4.shared.b16 {%0,%1,%2,%3}, [%4];"
                : "=r"(a[0]), "=r"(a[1]), "=r"(a[2]), "=r"(a[3])
                : "r"(abuf + kk * 2));
#pragma unroll
            for (int nt = 0; nt < 4; nt++) {
                int n0 = wn * 64 + nt * 16;
                unsigned baddr = bbuf + (kk + b_rowsel) * ROWB
                                      + (n0 + b_colsel) * 2;
                unsigned bb[4];
                asm volatile(
                    "ldmatrix.sync.aligned.m8n8.x4.trans.shared.b16 "
                    "{%0,%1,%2,%3}, [%4];"
                    : "=r"(bb[0]), "=r"(bb[1]), "=r"(bb[2]), "=r"(bb[3])
                    : "r"(baddr));
                mma16816(acc[nt * 2 + 0], a, bb[0], bb[1]);
                mma16816(acc[nt * 2 + 1], a, bb[2], bb[3]);
            }
        }

        if (c + 1 < IN_DIM / CT) {
            __nv_bfloat16* Ad = As + (buf ^ 1) * (RT * APAD);
#pragma unroll
            for (int p = 0; p < 8; p++) {
                int idx = t + p * NTH;
                int r = idx >> 5, c4 = idx & 31;
                __nv_bfloat162* dst = (__nv_bfloat162*)&Ad[r * APAD + c4 * 4];
                dst[0] = __float22bfloat162_rn(make_float2(av[p].x, av[p].y));
                dst[1] = __float22bfloat162_rn(make_float2(av[p].z, av[p].w));
            }
            asm volatile("cp.async.wait_group 0;");
        }
        __syncthreads();
    }

    const int g = lane >> 2, q = lane & 3;
    const int r0 = m0 + wm * 16 + g;
    const int r1 = r0 + 8;
#pragma unroll
    for (int m = 0; m < 8; m++) {
        int col = wn * 64 + m * 8 + 2 * q;
        g_Whb[(size_t)r0 * H_DIM + col]     = __float2bfloat16(acc[m][0] + sbias[col]);
        g_Whb[(size_t)r0 * H_DIM + col + 1] = __float2bfloat16(acc[m][1] + sbias[col + 1]);
        g_Whb[(size_t)r1 * H_DIM + col]     = __float2bfloat16(acc[m][2] + sbias[col]);
        g_Whb[(size_t)r1 * H_DIM + col + 1] = __float2bfloat16(acc[m][3] + sbias[col + 1]);
    }
}

// ---------------------------------------------------------------------------
// Kernel 3: per-row denom + bitmask (max-trick, branch-free, dual accumulators)
// ---------------------------------------------------------------------------
__global__ __launch_bounds__(256) void k_denom(const float* __restrict__ adj) {
    const int i    = blockIdx.x;
    const int t    = threadIdx.x;
    const int lane = t & 31;
    const int wid  = t >> 5;

    const float Ei  = __ldg(&g_E[i]);
    const float E2i = __ldg(&g_E2[i]);
    const float4* __restrict__ row4 = (const float4*)(adj + (size_t)i * N_NODES);
    const float4* __restrict__ E4   = (const float4*)g_E;
    const float4* __restrict__ E24  = (const float4*)g_E2;
    uint4* __restrict__ mrow = (uint4*)(g_mask + (size_t)i * MASK_WPR);

    float dsum0 = 0.f, dsum1 = 0.f;
#pragma unroll
    for (int step = 0; step < 8; step++) {
        int grp = wid * 8 + step;
        int c4  = grp * 32 + lane;
        float4 a4  = __ldcs(&row4[c4]);
        float4 Ej  = __ldg(&E4[c4]);
        float4 E2j = __ldg(&E24[c4]);
        unsigned nib = (a4.x != 0.f) | ((a4.y != 0.f) << 1)
                     | ((a4.z != 0.f) << 2) | ((a4.w != 0.f) << 3);
        unsigned b0 = __ballot_sync(0xffffffffu, nib & 1u);
        unsigned b1 = __ballot_sync(0xffffffffu, nib & 2u);
        unsigned b2 = __ballot_sync(0xffffffffu, nib & 4u);
        unsigned b3 = __ballot_sync(0xffffffffu, nib & 8u);
        if (lane == 0) mrow[grp] = make_uint4(b0, b1, b2, b3);

        dsum0 = fmaf(a4.x, fmaxf(Ei * Ej.x, E2i * E2j.x), dsum0);
        dsum1 = fmaf(a4.y, fmaxf(Ei * Ej.y, E2i * E2j.y), dsum1);
        dsum0 = fmaf(a4.z, fmaxf(Ei * Ej.z, E2i * E2j.z), dsum0);
        dsum1 = fmaf(a4.w, fmaxf(Ei * Ej.w, E2i * E2j.w), dsum1);
    }
    float dsum = dsum0 + dsum1;
#pragma unroll
    for (int o = 16; o; o >>= 1) dsum += __shfl_xor_sync(0xffffffffu, dsum, o);
    __shared__ float red[8];
    if (lane == 0) red[wid] = dsum;
    __syncthreads();
    if (t == 0) {
        float tot = 0.f;
#pragma unroll
        for (int w = 0; w < 8; w++) tot += red[w];
        g_inv[i] = (tot > 0.f) ? 1.f / tot : 0.f;
    }
}

// ---------------------------------------------------------------------------
// Kernel 4 (fused, PERSISTENT): grid 304, 2 CTAs/SM. Each CTA pops 8-chunk
// work units (ib, js) from g_ctr. Inner loop identical to R9 (double-As +
// double-Bs, one sync per chunk).
// ---------------------------------------------------------------------------
__device__ __forceinline__ void alpha_tile(
    __nv_bfloat16* Ad, float* __restrict__ alpha_out,
    const uint4* m4g, const float4* E4g, const float4* E24g,
    const float* sEA, const float* sEB,
    int i0, int jc, int wid, int lane)
{
    float4 Ej  = __ldg(&E4g [jc * 32 + lane]);
    float4 E2j = __ldg(&E24g[jc * 32 + lane]);
#pragma unroll
    for (int p = 0; p < 8; p++) {
        int r = wid * 8 + p;
        uint4 mw = __ldg(&m4g[(size_t)(i0 + r) * (MASK_WPR / 4) + jc]);
        float eA = sEA[r], eB = sEB[r];
        float4 ex;
        ex.x = ((mw.x >> lane) & 1u) ? fmaxf(eA * Ej.x, eB * E2j.x) : 0.f;
        ex.y = ((mw.y >> lane) & 1u) ? fmaxf(eA * Ej.y, eB * E2j.y) : 0.f;
        ex.z = ((mw.z >> lane) & 1u) ? fmaxf(eA * Ej.z, eB * E2j.z) : 0.f;
        ex.w = ((mw.w >> lane) & 1u) ? fmaxf(eA * Ej.w, eB * E2j.w) : 0.f;
        __stcs((float4*)(alpha_out + (size_t)(i0 + r) * N_NODES
                         + (size_t)jc * CT) + lane, ex);
        __nv_bfloat162* dst = (__nv_bfloat162*)&Ad[r * APAD + lane * 4];
        dst[0] = __float22bfloat162_rn(make_float2(ex.x, ex.y));
        dst[1] = __float22bfloat162_rn(make_float2(ex.z, ex.w));
    }
}

__global__ __launch_bounds__(NTH, 2) void k_fused(float* __restrict__ alpha_out) {
    extern __shared__ char smem[];
    __nv_bfloat16* As   = (__nv_bfloat16*)smem;           // 2 buffers
    float*         sEA  = (float*)(smem + OFF_SL);        // E[i]*inv
    float*         sEB  = sEA + RT;                       // E2[i]*inv
    unsigned*      sUnit = (unsigned*)(sEB + RT);

    const int t    = threadIdx.x;
    const int lane = t & 31;
    const int wid  = t >> 5;                 // 0..7

    const unsigned as_base = (unsigned)__cvta_generic_to_shared(As);
    const unsigned bs_base = (unsigned)__cvta_generic_to_shared(smem + OFF_BS);

    const float4* E4g  = (const float4*)g_E;
    const float4* E24g = (const float4*)g_E2;
    const uint4*  m4g  = (const uint4*)g_mask;

    const int wm = wid >> 1;     // 0..3 -> rows wm*16
    const int wn = wid & 1;      // 0..1 -> cols wn*64
    const unsigned a_off0 = (wm * 16 + (lane & 15)) * ROWB + ((lane >> 4) * 8) * 2;
    const unsigned b_rowsel = (lane & 15);
    const unsigned b_colsel = (lane >> 4) * 8;
    const int g = lane >> 2, q = lane & 3;

    while (true) {
        if (t == 0) *sUnit = atomicAdd(&g_ctr, 1u);
        __syncthreads();                  // also fences prior unit's smem reads
        const unsigned unit = *sUnit;
        if (unit >= NUNITS) break;

        const int ib = unit & 127;
        const int js = unit >> 7;         // 0..7
        const int i0 = ib * RT;
        const int c0 = js * CHUNKS;

        if (t < RT) {
            float inv = g_inv[i0 + t];
            sEA[t] = g_E [i0 + t] * inv;
            sEB[t] = g_E2[i0 + t] * inv;
        }

        // prologue: Bs chunk c0 -> buffer 0
        {
            const char* src = (const char*)(g_Whb + (size_t)c0 * CT * H_DIM);
#pragma unroll
            for (int p = 0; p < 8; p++) {
                int idx = t + p * NTH;
                int jr = idx >> 4, u = idx & 15;
                cp16(bs_base + jr * ROWB + u * 16, src + idx * 16);
            }
            asm volatile("cp.async.commit_group;");
        }
        __syncthreads();   // tables ready

        alpha_tile(As, alpha_out, m4g, E4g, E24g, sEA, sEB, i0, c0, wid, lane);
        asm volatile("cp.async.wait_group 0;");
        __syncthreads();

        float acc[8][4];
#pragma unroll
        for (int n = 0; n < 8; n++)
#pragma unroll
            for (int c = 0; c < 4; c++) acc[n][c] = 0.f;

#pragma unroll 1
        for (int cc = 0; cc < CHUNKS; cc++) {
            const int buf = cc & 1;
            const int jc  = c0 + cc;

            if (cc + 1 < CHUNKS) {
                const char* src = (const char*)(g_Whb + (size_t)(jc + 1) * CT * H_DIM);
                const unsigned bdst = bs_base + (buf ^ 1) * BS_BYTES;
#pragma unroll
                for (int p = 0; p < 8; p++) {
                    int idx = t + p * NTH;
                    int jr = idx >> 4, u = idx & 15;
                    cp16(bdst + jr * ROWB + u * 16, src + idx * 16);
                }
                asm volatile("cp.async.commit_group;");
                alpha_tile(As + (buf ^ 1) * (RT * APAD), alpha_out,
                           m4g, E4g, E24g, sEA, sEB, i0, jc + 1, wid, lane);
            }

            const unsigned abuf = as_base + buf * AS_BYTES + a_off0;
            const unsigned bbuf = bs_base + buf * BS_BYTES;
#pragma unroll
            for (int kk = 0; kk < CT; kk += 16) {
                unsigned a[4];
                asm volatile(
                    "ldmatrix.sync.aligned.m8n8.x4.shared.b16 {%0,%1,%2,%3}, [%4];"
                    : "=r"(a[0]), "=r"(a[1]), "=r"(a[2]), "=r"(a[3])
                    : "r"(abuf + kk * 2));
#pragma unroll
                for (int nt = 0; nt < 4; nt++) {
                    int n0 = wn * 64 + nt * 16;
                    unsigned baddr = bbuf + (kk + b_rowsel) * ROWB
                                          + (n0 + b_colsel) * 2;
                    unsigned bb[4];
                    asm volatile(
                        "ldmatrix.sync.aligned.m8n8.x4.trans.shared.b16 "
                        "{%0,%1,%2,%3}, [%4];"
                        : "=r"(bb[0]), "=r"(bb[1]), "=r"(bb[2]), "=r"(bb[3])
                        : "r"(baddr));
                    mma16816(acc[nt * 2 + 0], a, bb[0], bb[1]);
                    mma16816(acc[nt * 2 + 1], a, bb[2], bb[3]);
                }
            }

            if (cc + 1 < CHUNKS)
                asm volatile("cp.async.wait_group 0;");
            __syncthreads();
        }

        // epilogue: write fp32 partials for this unit
        float* part = g_part + (size_t)js * N_NODES * H_DIM;
        const size_t r0 = (size_t)(i0 + wm * 16 + g) * H_DIM;
        const size_t r1 = r0 + 8 * H_DIM;
#pragma unroll
        for (int m = 0; m < 8; m++) {
            int col = wn * 64 + m * 8 + 2 * q;
            part[r0 + col]     = acc[m][0];
            part[r0 + col + 1] = acc[m][1];
            part[r1 + col]     = acc[m][2];
            part[r1 + col + 1] = acc[m][3];
        }
    }
}

// ---------------------------------------------------------------------------
// Kernel 5: z = sigmoid(sum of JSPLIT partials)
// ---------------------------------------------------------------------------
__global__ __launch_bounds__(256) void k_z(float* __restrict__ z_out) {
    int idx = blockIdx.x * 256 + threadIdx.x;
    float4 acc = ((const float4*)g_part)[idx];
#pragma unroll
    for (int js = 1; js < JSPLIT; js++) {
        float4 v = ((const float4*)(g_part + (size_t)js * N_NODES * H_DIM))[idx];
        acc.x += v.x; acc.y += v.y; acc.z += v.z; acc.w += v.w;
    }
    float4 z;
    z.x = 1.f / (1.f + __expf(-acc.x));
    z.y = 1.f / (1.f + __expf(-acc.y));
    z.z = 1.f / (1.f + __expf(-acc.z));
    z.w = 1.f / (1.f + __expf(-acc.w));
    ((float4*)z_out)[idx] = z;
}

// ---------------------------------------------------------------------------
extern "C" void kernel_launch(void* const* d_in, const int* in_sizes, int n_in,
                              void* d_out, int out_size) {
    const float* h   = (const float*)d_in[0];  // (8192, 512)
    const float* adj = (const float*)d_in[1];  // (8192, 8192)
    const float* W   = (const float*)d_in[2];  // (128, 512)
    const float* b   = (const float*)d_in[3];  // (128,)
    const float* a   = (const float*)d_in[4];  // (1, 128)

    float* z_out     = (float*)d_out;
    float* alpha_out = z_out + (size_t)N_NODES * H_DIM;

    k_prep<<<257, 256>>>(W, a);
    k_s<<<N_NODES / 8, 256>>>(h);

    cudaFuncSetAttribute(k_gemm_tc, cudaFuncAttributeMaxDynamicSharedMemorySize,
                         GT_SMEM);
    k_gemm_tc<<<N_NODES / RT, NTH, GT_SMEM>>>(h, b);

    k_denom<<<N_NODES, 256>>>(adj);

    cudaFuncSetAttribute(k_fused, cudaFuncAttributeMaxDynamicSharedMemorySize,
                         SMEM_TOTAL);
    k_fused<<<PGRID, NTH, SMEM_TOTAL>>>(alpha_out);

    k_z<<<(N_NODES * H_DIM / 4) / 256, 256>>>(z_out);
}